// round 1
// baseline (speedup 1.0000x reference)
#include <cuda_runtime.h>
#include <math.h>

#define DD 256
#define BB 4
#define NN 512

// Scratch: xp = x @ Wx  (B*N, D);  ypb = y @ Wy + b1  (B*N, D)
__device__ float g_xp[BB * NN * DD];
__device__ float g_ypb[BB * NN * DD];

// ---------------------------------------------------------------------------
// GEMM: out[M x 256] = X[M x 256] @ W[256 x 256] (+ optional bias[256])
// M = 2048, tiles 64x64, BK=16, 256 threads, 4x4 per thread.
// ---------------------------------------------------------------------------
__global__ __launch_bounds__(256) void gemm_kernel(
    const float* __restrict__ X,
    const float* __restrict__ W,
    const float* __restrict__ bias,
    int has_bias,
    int dst_sel)   // 0 -> g_xp, 1 -> g_ypb
{
    __shared__ float As[16][68];
    __shared__ float Bs[16][68];

    float* out = dst_sel ? g_ypb : g_xp;

    const int tx = threadIdx.x;     // 0..15
    const int ty = threadIdx.y;     // 0..15
    const int t  = ty * 16 + tx;
    const int m0 = blockIdx.y * 64;
    const int n0 = blockIdx.x * 64;

    float acc[4][4] = {};

    for (int k0 = 0; k0 < 256; k0 += 16) {
        // A tile: 64 rows x 16 k  (transposed into smem)
        {
            int m  = t >> 2;              // 0..63
            int kq = (t & 3) * 4;         // 0,4,8,12
            float4 v = *(const float4*)&X[(m0 + m) * 256 + k0 + kq];
            As[kq + 0][m] = v.x;
            As[kq + 1][m] = v.y;
            As[kq + 2][m] = v.z;
            As[kq + 3][m] = v.w;
        }
        // B tile: 16 k x 64 cols
        {
            int k  = t >> 4;              // 0..15
            int nq = (t & 15) * 4;        // 0..60
            float4 v = *(const float4*)&W[(k0 + k) * 256 + n0 + nq];
            *(float4*)&Bs[k][nq] = v;
        }
        __syncthreads();

        #pragma unroll
        for (int kk = 0; kk < 16; ++kk) {
            float4 a = *(const float4*)&As[kk][ty * 4];
            float4 b = *(const float4*)&Bs[kk][tx * 4];
            float av[4] = {a.x, a.y, a.z, a.w};
            float bv[4] = {b.x, b.y, b.z, b.w};
            #pragma unroll
            for (int i = 0; i < 4; ++i)
                #pragma unroll
                for (int j = 0; j < 4; ++j)
                    acc[i][j] = fmaf(av[i], bv[j], acc[i][j]);
        }
        __syncthreads();
    }

    #pragma unroll
    for (int i = 0; i < 4; ++i) {
        int m = m0 + ty * 4 + i;
        #pragma unroll
        for (int j = 0; j < 4; ++j) {
            int n = n0 + tx * 4 + j;
            float v = acc[i][j];
            if (has_bias) v += bias[n];
            out[m * 256 + n] = v;
        }
    }
}

// ---------------------------------------------------------------------------
// Cross kernel: each block = one (b, 32n x 32m) tile.
// smem: xs[d][n] and ys[d][m], stride 33 (conflict-free), plus ws[256].
// Each thread (16x16 block) computes a 2x2 micro-tile of outputs.
// ---------------------------------------------------------------------------
__device__ __forceinline__ float gelu_exact(float v) {
    return 0.5f * v * (1.0f + erff(v * 0.70710678118654752f));
}

#define SROW 33

__global__ __launch_bounds__(256) void cross_kernel(
    const float* __restrict__ W2,
    const float* __restrict__ b2,
    float* __restrict__ out)
{
    extern __shared__ float sm[];
    float* xs = sm;                    // [256][33]
    float* ys = sm + 256 * SROW;       // [256][33]
    float* ws = sm + 2 * 256 * SROW;   // [256]

    const int tx = threadIdx.x;        // 0..15 -> m
    const int ty = threadIdx.y;        // 0..15 -> n
    const int t  = ty * 16 + tx;
    const int bz = blockIdx.z;
    const int n0 = blockIdx.y * 32;
    const int m0 = blockIdx.x * 32;

    const float* xp = g_xp  + (bz * NN + n0) * DD;
    const float* yp = g_ypb + (bz * NN + m0) * DD;

    // Fill: thread -> (row r 0..31, chunk cq 0..7); d = 32*it + 4*cq
    // Global: per-warp 4 rows x 8 contiguous 16B segs. STS: banks (4cq+j+r)%32
    // all distinct within warp -> conflict-free transpose.
    {
        int r  = t >> 3;    // 0..31
        int cq = t & 7;     // 0..7
        #pragma unroll
        for (int it = 0; it < 8; ++it) {
            int d = 32 * it + 4 * cq;
            float4 v = *(const float4*)&xp[r * 256 + d];
            xs[(d + 0) * SROW + r] = v.x;
            xs[(d + 1) * SROW + r] = v.y;
            xs[(d + 2) * SROW + r] = v.z;
            xs[(d + 3) * SROW + r] = v.w;
            float4 u = *(const float4*)&yp[r * 256 + d];
            ys[(d + 0) * SROW + r] = u.x;
            ys[(d + 1) * SROW + r] = u.y;
            ys[(d + 2) * SROW + r] = u.z;
            ys[(d + 3) * SROW + r] = u.w;
        }
        ws[t] = W2[t];
    }
    __syncthreads();

    float a00 = 0.f, a01 = 0.f, a10 = 0.f, a11 = 0.f;

    #pragma unroll 4
    for (int d = 0; d < 256; ++d) {
        float x0 = xs[d * SROW + 2 * ty];
        float x1 = xs[d * SROW + 2 * ty + 1];
        float y0 = ys[d * SROW + 2 * tx];
        float y1 = ys[d * SROW + 2 * tx + 1];
        float w  = ws[d];
        a00 = fmaf(gelu_exact(x0 + y0), w, a00);
        a01 = fmaf(gelu_exact(x0 + y1), w, a01);
        a10 = fmaf(gelu_exact(x1 + y0), w, a10);
        a11 = fmaf(gelu_exact(x1 + y1), w, a11);
    }

    const float bb = b2[0];
    const int n = n0 + 2 * ty;
    const int m = m0 + 2 * tx;
    float* orow = out + (size_t)(bz * NN + n) * NN + m;
    orow[0]       = a00 + bb;
    orow[1]       = a01 + bb;
    orow[NN]      = a10 + bb;
    orow[NN + 1]  = a11 + bb;
}

// ---------------------------------------------------------------------------
extern "C" void kernel_launch(void* const* d_in, const int* in_sizes, int n_in,
                              void* d_out, int out_size)
{
    const float* x  = (const float*)d_in[0];
    const float* y  = (const float*)d_in[1];
    const float* W1 = (const float*)d_in[2];
    const float* b1 = (const float*)d_in[3];
    const float* W2 = (const float*)d_in[4];
    const float* b2 = (const float*)d_in[5];
    float* out = (float*)d_out;

    (void)in_sizes; (void)n_in; (void)out_size;

    const int smem_cross = (2 * 256 * SROW + 256) * (int)sizeof(float);
    cudaFuncSetAttribute(cross_kernel,
                         cudaFuncAttributeMaxDynamicSharedMemorySize,
                         smem_cross);

    dim3 gblk(16, 16);
    dim3 ggrid(4, 32);   // 256/64 cols, 2048/64 rows
    // xp = x @ W1[0:256]
    gemm_kernel<<<ggrid, gblk>>>(x, W1, nullptr, 0, 0);
    // ypb = y @ W1[256:512] + b1
    gemm_kernel<<<ggrid, gblk>>>(y, W1 + 256 * 256, b1, 1, 1);

    dim3 cblk(16, 16);
    dim3 cgrid(16, 16, 4);  // (m-tiles, n-tiles, batch)
    cross_kernel<<<cgrid, cblk, smem_cross>>>(W2, b2, out);
}

// round 2
// speedup vs baseline: 2.7541x; 2.7541x over previous
#include <cuda_runtime.h>
#include <math.h>

#define DD 256
#define BB 4
#define NN 512

// Scratch: xp = x @ Wx  (B*N, D);  ypb = y @ Wy + b1  (B*N, D)
__device__ float g_xp[BB * NN * DD];
__device__ float g_ypb[BB * NN * DD];

// ---------------------------------------------------------------------------
// Merged GEMM: z=0: g_xp = x @ W1[0:256];  z=1: g_ypb = y @ W1[256:512] + b1
// M = 2048, tiles 64x64, BK=16, 256 threads, 4x4 per thread.
// ---------------------------------------------------------------------------
__global__ __launch_bounds__(256) void gemm_kernel(
    const float* __restrict__ x,
    const float* __restrict__ y,
    const float* __restrict__ W1,
    const float* __restrict__ b1)
{
    __shared__ float As[16][68];
    __shared__ float Bs[16][68];

    const int sel = blockIdx.z;
    const float* X = sel ? y : x;
    const float* W = sel ? (W1 + 256 * 256) : W1;
    float* out = sel ? g_ypb : g_xp;

    const int tx = threadIdx.x;     // 0..15
    const int ty = threadIdx.y;     // 0..15
    const int t  = ty * 16 + tx;
    const int m0 = blockIdx.y * 64;
    const int n0 = blockIdx.x * 64;

    float acc[4][4] = {};

    for (int k0 = 0; k0 < 256; k0 += 16) {
        // A tile: 64 rows x 16 k  (transposed into smem)
        {
            int m  = t >> 2;              // 0..63
            int kq = (t & 3) * 4;         // 0,4,8,12
            float4 v = *(const float4*)&X[(m0 + m) * 256 + k0 + kq];
            As[kq + 0][m] = v.x;
            As[kq + 1][m] = v.y;
            As[kq + 2][m] = v.z;
            As[kq + 3][m] = v.w;
        }
        // B tile: 16 k x 64 cols
        {
            int k  = t >> 4;              // 0..15
            int nq = (t & 15) * 4;        // 0..60
            float4 v = *(const float4*)&W[(k0 + k) * 256 + n0 + nq];
            *(float4*)&Bs[k][nq] = v;
        }
        __syncthreads();

        #pragma unroll
        for (int kk = 0; kk < 16; ++kk) {
            float4 a = *(const float4*)&As[kk][ty * 4];
            float4 b = *(const float4*)&Bs[kk][tx * 4];
            float av[4] = {a.x, a.y, a.z, a.w};
            float bv[4] = {b.x, b.y, b.z, b.w};
            #pragma unroll
            for (int i = 0; i < 4; ++i)
                #pragma unroll
                for (int j = 0; j < 4; ++j)
                    acc[i][j] = fmaf(av[i], bv[j], acc[i][j]);
        }
        __syncthreads();
    }

    #pragma unroll
    for (int i = 0; i < 4; ++i) {
        int m = m0 + ty * 4 + i;
        #pragma unroll
        for (int j = 0; j < 4; ++j) {
            int n = n0 + tx * 4 + j;
            float v = acc[i][j];
            if (sel) v += b1[n];
            out[m * 256 + n] = v;
        }
    }
}

// ---------------------------------------------------------------------------
// Cross kernel: each block = one (b, 32n x 32m) tile.
// tanh-form gelu with MUFU.TANH; 0.5 factor folded into ws[].
// ---------------------------------------------------------------------------
__device__ __forceinline__ float tanh_fast(float v) {
    float r;
    asm("tanh.approx.f32 %0, %1;" : "=f"(r) : "f"(v));
    return r;
}

#define GC0 0.79788456080286536f          // sqrt(2/pi)
#define GC1 0.03567740813636141f          // sqrt(2/pi)*0.044715

#define SROW 33

__global__ __launch_bounds__(256) void cross_kernel(
    const float* __restrict__ W2,
    const float* __restrict__ b2,
    float* __restrict__ out)
{
    extern __shared__ float sm[];
    float* xs = sm;                    // [256][33], d-major
    float* ys = sm + 256 * SROW;       // [256][33]
    float* ws = sm + 2 * 256 * SROW;   // [256]  (0.5*W2)

    const int tx = threadIdx.x;        // 0..15 -> m
    const int ty = threadIdx.y;        // 0..15 -> n
    const int t  = ty * 16 + tx;
    const int bz = blockIdx.z;
    const int n0 = blockIdx.y * 32;
    const int m0 = blockIdx.x * 32;

    const float* xp = g_xp  + (bz * NN + n0) * DD;
    const float* yp = g_ypb + (bz * NN + m0) * DD;

    // Conflict-free transpose fill (stride-33)
    {
        int r  = t >> 3;    // 0..31
        int cq = t & 7;     // 0..7
        #pragma unroll
        for (int it = 0; it < 8; ++it) {
            int d = 32 * it + 4 * cq;
            float4 v = *(const float4*)&xp[r * 256 + d];
            xs[(d + 0) * SROW + r] = v.x;
            xs[(d + 1) * SROW + r] = v.y;
            xs[(d + 2) * SROW + r] = v.z;
            xs[(d + 3) * SROW + r] = v.w;
            float4 u = *(const float4*)&yp[r * 256 + d];
            ys[(d + 0) * SROW + r] = u.x;
            ys[(d + 1) * SROW + r] = u.y;
            ys[(d + 2) * SROW + r] = u.z;
            ys[(d + 3) * SROW + r] = u.w;
        }
        ws[t] = 0.5f * W2[t];
    }
    __syncthreads();

    float a00 = 0.f, a01 = 0.f, a10 = 0.f, a11 = 0.f;

    #pragma unroll 8
    for (int d = 0; d < 256; ++d) {
        float x0 = xs[d * SROW + 2 * ty];
        float x1 = xs[d * SROW + 2 * ty + 1];
        float y0 = ys[d * SROW + 2 * tx];
        float y1 = ys[d * SROW + 2 * tx + 1];
        float w  = ws[d];

        #define GELU_ACC(ACC, XV, YV)                       \
        {                                                   \
            float h = (XV) + (YV);                          \
            float q = h * h;                                \
            float s = fmaf(q, GC1, GC0);                    \
            float u = h * s;                                \
            float T = tanh_fast(u);                         \
            float g = fmaf(h, T, h);                        \
            ACC = fmaf(g, w, ACC);                          \
        }

        GELU_ACC(a00, x0, y0)
        GELU_ACC(a01, x0, y1)
        GELU_ACC(a10, x1, y0)
        GELU_ACC(a11, x1, y1)
        #undef GELU_ACC
    }

    const float bb = b2[0];
    const int n = n0 + 2 * ty;
    const int m = m0 + 2 * tx;
    float* orow = out + (size_t)(bz * NN + n) * NN + m;
    orow[0]       = a00 + bb;
    orow[1]       = a01 + bb;
    orow[NN]      = a10 + bb;
    orow[NN + 1]  = a11 + bb;
}

// ---------------------------------------------------------------------------
extern "C" void kernel_launch(void* const* d_in, const int* in_sizes, int n_in,
                              void* d_out, int out_size)
{
    const float* x  = (const float*)d_in[0];
    const float* y  = (const float*)d_in[1];
    const float* W1 = (const float*)d_in[2];
    const float* b1 = (const float*)d_in[3];
    const float* W2 = (const float*)d_in[4];
    const float* b2 = (const float*)d_in[5];
    float* out = (float*)d_out;

    (void)in_sizes; (void)n_in; (void)out_size;

    const int smem_cross = (2 * 256 * SROW + 256) * (int)sizeof(float);
    cudaFuncSetAttribute(cross_kernel,
                         cudaFuncAttributeMaxDynamicSharedMemorySize,
                         smem_cross);

    dim3 gblk(16, 16);
    dim3 ggrid(4, 32, 2);   // both GEMMs in one launch
    gemm_kernel<<<ggrid, gblk>>>(x, y, W1, b1);

    dim3 cblk(16, 16);
    dim3 cgrid(16, 16, 4);  // (m-tiles, n-tiles, batch)
    cross_kernel<<<cgrid, cblk, smem_cross>>>(W2, b2, out);
}

// round 4
// speedup vs baseline: 2.7818x; 1.0100x over previous
#include <cuda_runtime.h>
#include <math.h>

#define DD 256
#define BATCH 4
#define NN 512

typedef unsigned long long u64;

// Scratch: xp = x @ Wx  (B*N, D);  ypb = y @ Wy + b1  (B*N, D)
__device__ float g_xp[BATCH * NN * DD];
__device__ float g_ypb[BATCH * NN * DD];

// ---- f32x2 packed-math primitives (fma pipe, 2 fp32 per slot) -------------
#define F2FMA(D_, A_, B_, C_) \
    asm("fma.rn.f32x2 %0, %1, %2, %3;" : "=l"(D_) : "l"(A_), "l"(B_), "l"(C_))
#define F2ADD(D_, A_, B_) \
    asm("add.rn.f32x2 %0, %1, %2;" : "=l"(D_) : "l"(A_), "l"(B_))
#define F2MUL(D_, A_, B_) \
    asm("mul.rn.f32x2 %0, %1, %2;" : "=l"(D_) : "l"(A_), "l"(B_))
#define PK(D_, LO_, HI_) \
    asm("mov.b64 %0, {%1, %2};" : "=l"(D_) : "f"(LO_), "f"(HI_))
#define UNPK(LO_, HI_, S_) \
    asm("mov.b64 {%0, %1}, %2;" : "=f"(LO_), "=f"(HI_) : "l"(S_))

__device__ __forceinline__ float tanh_fast(float v) {
    float r;
    asm("tanh.approx.f32 %0, %1;" : "=f"(r) : "f"(v));
    return r;
}

#define GC0 0.79788456080286536f          // sqrt(2/pi)
#define GC1 0.03567740813636141f          // sqrt(2/pi)*0.044715

// ---------------------------------------------------------------------------
// Merged GEMM: z=0: g_xp = x @ W1[0:256];  z=1: g_ypb = y @ W1[256:512] + b1
// M=2048, tiles 64x64, BK=16, 256 threads, 4x4 per thread, f32x2 inner.
// Asd holds each A value duplicated so LDS.64 yields (a,a) broadcast pairs.
// ---------------------------------------------------------------------------
__global__ __launch_bounds__(256) void gemm_kernel(
    const float* __restrict__ x,
    const float* __restrict__ y,
    const float* __restrict__ W1,
    const float* __restrict__ b1)
{
    __shared__ float Asd[16][138];   // [k][2m], [k][2m+1] = A[m][k] (dup)
    __shared__ float Bs[16][68];

    const int sel = blockIdx.z;
    const float* X = sel ? y : x;
    const float* W = sel ? (W1 + 256 * 256) : W1;
    float* out = sel ? g_ypb : g_xp;

    const int tx = threadIdx.x;     // 0..15
    const int ty = threadIdx.y;     // 0..15
    const int t  = ty * 16 + tx;
    const int m0 = blockIdx.y * 64;
    const int n0 = blockIdx.x * 64;

    u64 acc[4][2];
    #pragma unroll
    for (int i = 0; i < 4; ++i) { acc[i][0] = 0ull; acc[i][1] = 0ull; }

    for (int k0 = 0; k0 < 256; k0 += 16) {
        // A tile: 64 rows x 16 k, transposed + duplicated
        {
            int m  = t >> 2;              // 0..63
            int kq = (t & 3) * 4;         // 0,4,8,12
            float4 v = *(const float4*)&X[(m0 + m) * 256 + k0 + kq];
            u64 p;
            PK(p, v.x, v.x); *(u64*)&Asd[kq + 0][2 * m] = p;
            PK(p, v.y, v.y); *(u64*)&Asd[kq + 1][2 * m] = p;
            PK(p, v.z, v.z); *(u64*)&Asd[kq + 2][2 * m] = p;
            PK(p, v.w, v.w); *(u64*)&Asd[kq + 3][2 * m] = p;
        }
        // B tile: 16 k x 64 cols
        {
            int k  = t >> 4;              // 0..15
            int nq = (t & 15) * 4;        // 0..60
            float4 v = *(const float4*)&W[(k0 + k) * 256 + n0 + nq];
            *(float4*)&Bs[k][nq] = v;
        }
        __syncthreads();

        #pragma unroll
        for (int kk = 0; kk < 16; ++kk) {
            const float* ar = &Asd[kk][0];
            const float* br = &Bs[kk][0];
            u64 B0 = *(const u64*)&br[tx * 4];
            u64 B1 = *(const u64*)&br[tx * 4 + 2];
            #pragma unroll
            for (int i = 0; i < 4; ++i) {
                u64 Ai = *(const u64*)&ar[2 * (ty * 4 + i)];
                F2FMA(acc[i][0], Ai, B0, acc[i][0]);
                F2FMA(acc[i][1], Ai, B1, acc[i][1]);
            }
        }
        __syncthreads();
    }

    #pragma unroll
    for (int i = 0; i < 4; ++i) {
        int m = m0 + ty * 4 + i;
        int n = n0 + tx * 4;
        float c0, c1, c2, c3;
        UNPK(c0, c1, acc[i][0]);
        UNPK(c2, c3, acc[i][1]);
        if (sel) {
            c0 += b1[n + 0]; c1 += b1[n + 1];
            c2 += b1[n + 2]; c3 += b1[n + 3];
        }
        float4 o = {c0, c1, c2, c3};
        *(float4*)&out[m * 256 + n] = o;
    }
}

// ---------------------------------------------------------------------------
// Cross kernel: block = (b, 32n x 32m) tile; thread = 2x2 micro-tile packed
// as two f32x2 groups. tanh-form gelu, 0.5 folded into ws.
// ---------------------------------------------------------------------------
#define SX 34   // row stride (floats): even for LDS.64 align, conflict-free fill

__global__ __launch_bounds__(256) void cross_kernel(
    const float* __restrict__ W2,
    const float* __restrict__ b2,
    float* __restrict__ out)
{
    extern __shared__ float sm[];
    float* xs  = sm;                     // [256][SX], d-major, xs[d*SX + i]
    float* ys  = sm + 256 * SX;          // [256][SX]
    float* ws2 = sm + 2 * 256 * SX;      // [512] duplicated (0.5*W2 pairs)

    const int tx = threadIdx.x;        // 0..15 -> m
    const int ty = threadIdx.y;        // 0..15 -> n
    const int t  = ty * 16 + tx;
    const int bz = blockIdx.z;
    const int n0 = blockIdx.y * 32;
    const int m0 = blockIdx.x * 32;

    const float* xp = g_xp  + (bz * NN + n0) * DD;
    const float* yp = g_ypb + (bz * NN + m0) * DD;

    // Conflict-free transpose fill (bank = (2d + r) mod 32, all distinct)
    {
        int r  = t >> 3;    // 0..31
        int cq = t & 7;     // 0..7
        #pragma unroll
        for (int it = 0; it < 8; ++it) {
            int d = 32 * it + 4 * cq;
            float4 v = *(const float4*)&xp[r * 256 + d];
            xs[(d + 0) * SX + r] = v.x;
            xs[(d + 1) * SX + r] = v.y;
            xs[(d + 2) * SX + r] = v.z;
            xs[(d + 3) * SX + r] = v.w;
            float4 u = *(const float4*)&yp[r * 256 + d];
            ys[(d + 0) * SX + r] = u.x;
            ys[(d + 1) * SX + r] = u.y;
            ys[(d + 2) * SX + r] = u.z;
            ys[(d + 3) * SX + r] = u.w;
        }
        float wv = 0.5f * W2[t];
        u64 wp; PK(wp, wv, wv);
        *(u64*)&ws2[2 * t] = wp;
    }
    __syncthreads();

    u64 C0P, C1P;
    PK(C0P, GC0, GC0);
    PK(C1P, GC1, GC1);

    u64 acc0 = 0ull, acc1 = 0ull;   // (a00,a01), (a10,a11)

    const float* xsp = xs + 2 * ty;
    const float* ysp = ys + 2 * tx;

    #pragma unroll 8
    for (int d = 0; d < 256; ++d) {
        float2 xv = *(const float2*)&xsp[d * SX];
        u64 Y = *(const u64*)&ysp[d * SX];
        u64 W = *(const u64*)&ws2[2 * d];
        u64 X0, X1;
        PK(X0, xv.x, xv.x);
        PK(X1, xv.y, xv.y);

        #define GEL2(ACC, XB)                               \
        {                                                   \
            u64 H, Q, S, U, T, G;                           \
            float u0, u1, t0, t1;                           \
            F2ADD(H, XB, Y);                                \
            F2MUL(Q, H, H);                                 \
            F2FMA(S, Q, C1P, C0P);                          \
            F2MUL(U, H, S);                                 \
            UNPK(u0, u1, U);                                \
            t0 = tanh_fast(u0);                             \
            t1 = tanh_fast(u1);                             \
            PK(T, t0, t1);                                  \
            F2FMA(G, H, T, H);                              \
            F2FMA(ACC, G, W, ACC);                          \
        }

        GEL2(acc0, X0)
        GEL2(acc1, X1)
        #undef GEL2
    }

    const float bb = b2[0];
    u64 bpair; PK(bpair, bb, bb);
    F2ADD(acc0, acc0, bpair);
    F2ADD(acc1, acc1, bpair);

    const int n = n0 + 2 * ty;
    const int m = m0 + 2 * tx;
    float* orow = out + (size_t)(bz * NN + n) * NN + m;
    *(u64*)&orow[0]  = acc0;
    *(u64*)&orow[NN] = acc1;
}

// ---------------------------------------------------------------------------
extern "C" void kernel_launch(void* const* d_in, const int* in_sizes, int n_in,
                              void* d_out, int out_size)
{
    const float* x  = (const float*)d_in[0];
    const float* y  = (const float*)d_in[1];
    const float* W1 = (const float*)d_in[2];
    const float* b1 = (const float*)d_in[3];
    const float* W2 = (const float*)d_in[4];
    const float* b2 = (const float*)d_in[5];
    float* out = (float*)d_out;

    (void)in_sizes; (void)n_in; (void)out_size;

    const int smem_cross = (2 * 256 * SX + 512) * (int)sizeof(float);
    cudaFuncSetAttribute(cross_kernel,
                         cudaFuncAttributeMaxDynamicSharedMemorySize,
                         smem_cross);

    dim3 gblk(16, 16);
    dim3 ggrid(4, 32, 2);   // both GEMMs in one launch
    gemm_kernel<<<ggrid, gblk>>>(x, y, W1, b1);

    dim3 cblk(16, 16);
    dim3 cgrid(16, 16, 4);  // (m-tiles, n-tiles, batch)
    cross_kernel<<<cgrid, cblk, smem_cross>>>(W2, b2, out);
}

// round 5
// speedup vs baseline: 2.8137x; 1.0115x over previous
#include <cuda_runtime.h>
#include <math.h>

#define DD 256
#define BATCH 4
#define NN 512

typedef unsigned long long u64;

// Scratch: xp = x @ Wx  (B*N, D);  ypb = y @ Wy + b1  (B*N, D)
__device__ float g_xp[BATCH * NN * DD];
__device__ float g_ypb[BATCH * NN * DD];

// ---- f32x2 packed-math primitives (fma pipe, 2 fp32 per slot) -------------
#define F2FMA(D_, A_, B_, C_) \
    asm("fma.rn.f32x2 %0, %1, %2, %3;" : "=l"(D_) : "l"(A_), "l"(B_), "l"(C_))
#define F2ADD(D_, A_, B_) \
    asm("add.rn.f32x2 %0, %1, %2;" : "=l"(D_) : "l"(A_), "l"(B_))
#define F2MUL(D_, A_, B_) \
    asm("mul.rn.f32x2 %0, %1, %2;" : "=l"(D_) : "l"(A_), "l"(B_))
#define PK(D_, LO_, HI_) \
    asm("mov.b64 %0, {%1, %2};" : "=l"(D_) : "f"(LO_), "f"(HI_))
#define UNPK(LO_, HI_, S_) \
    asm("mov.b64 {%0, %1}, %2;" : "=f"(LO_), "=f"(HI_) : "l"(S_))

__device__ __forceinline__ float tanh_fast(float v) {
    float r;
    asm("tanh.approx.f32 %0, %1;" : "=f"(r) : "f"(v));
    return r;
}

#define GC0 0.79788456080286536f          // sqrt(2/pi)
#define GC1 0.03567740813636141f          // sqrt(2/pi)*0.044715

// ---------------------------------------------------------------------------
// Merged GEMM: z=0: g_xp = x @ W1[0:256];  z=1: g_ypb = y @ W1[256:512] + b1
// M=2048, tiles 64x64, BK=16, 256 threads, 4x4 per thread, f32x2 inner.
// ---------------------------------------------------------------------------
__global__ __launch_bounds__(256) void gemm_kernel(
    const float* __restrict__ x,
    const float* __restrict__ y,
    const float* __restrict__ W1,
    const float* __restrict__ b1)
{
    __shared__ float Asd[16][138];   // [k][2m], [k][2m+1] = A[m][k] (dup)
    __shared__ float Bs[16][68];

    const int sel = blockIdx.z;
    const float* X = sel ? y : x;
    const float* W = sel ? (W1 + 256 * 256) : W1;
    float* out = sel ? g_ypb : g_xp;

    const int tx = threadIdx.x;     // 0..15
    const int ty = threadIdx.y;     // 0..15
    const int t  = ty * 16 + tx;
    const int m0 = blockIdx.y * 64;
    const int n0 = blockIdx.x * 64;

    u64 acc[4][2];
    #pragma unroll
    for (int i = 0; i < 4; ++i) { acc[i][0] = 0ull; acc[i][1] = 0ull; }

    for (int k0 = 0; k0 < 256; k0 += 16) {
        {
            int m  = t >> 2;              // 0..63
            int kq = (t & 3) * 4;         // 0,4,8,12
            float4 v = *(const float4*)&X[(m0 + m) * 256 + k0 + kq];
            u64 p;
            PK(p, v.x, v.x); *(u64*)&Asd[kq + 0][2 * m] = p;
            PK(p, v.y, v.y); *(u64*)&Asd[kq + 1][2 * m] = p;
            PK(p, v.z, v.z); *(u64*)&Asd[kq + 2][2 * m] = p;
            PK(p, v.w, v.w); *(u64*)&Asd[kq + 3][2 * m] = p;
        }
        {
            int k  = t >> 4;              // 0..15
            int nq = (t & 15) * 4;        // 0..60
            float4 v = *(const float4*)&W[(k0 + k) * 256 + n0 + nq];
            *(float4*)&Bs[k][nq] = v;
        }
        __syncthreads();

        #pragma unroll
        for (int kk = 0; kk < 16; ++kk) {
            const float* ar = &Asd[kk][0];
            const float* br = &Bs[kk][0];
            u64 B0 = *(const u64*)&br[tx * 4];
            u64 B1 = *(const u64*)&br[tx * 4 + 2];
            #pragma unroll
            for (int i = 0; i < 4; ++i) {
                u64 Ai = *(const u64*)&ar[2 * (ty * 4 + i)];
                F2FMA(acc[i][0], Ai, B0, acc[i][0]);
                F2FMA(acc[i][1], Ai, B1, acc[i][1]);
            }
        }
        __syncthreads();
    }

    #pragma unroll
    for (int i = 0; i < 4; ++i) {
        int m = m0 + ty * 4 + i;
        int n = n0 + tx * 4;
        float c0, c1, c2, c3;
        UNPK(c0, c1, acc[i][0]);
        UNPK(c2, c3, acc[i][1]);
        if (sel) {
            c0 += b1[n + 0]; c1 += b1[n + 1];
            c2 += b1[n + 2]; c3 += b1[n + 3];
        }
        float4 o = {c0, c1, c2, c3};
        *(float4*)&out[m * 256 + n] = o;
    }
}

// ---------------------------------------------------------------------------
// Cross kernel: block = (b, 32n x 32m) tile; thread = 2x2 micro-tile packed
// as two f32x2 groups. d chunked 2x128 to halve smem -> 6 blocks/SM.
// ---------------------------------------------------------------------------
#define SX 34       // row stride (floats): even for LDS.64 align, conflict-free
#define DCH 128     // d-chunk

__global__ __launch_bounds__(256, 6) void cross_kernel(
    const float* __restrict__ W2,
    const float* __restrict__ b2,
    float* __restrict__ out)
{
    extern __shared__ float sm[];
    float* xs  = sm;                     // [DCH][SX], d-major within chunk
    float* ys  = sm + DCH * SX;          // [DCH][SX]
    float* ws2 = sm + 2 * DCH * SX;      // [512] duplicated (0.5*W2 pairs)

    const int tx = threadIdx.x;        // 0..15 -> m
    const int ty = threadIdx.y;        // 0..15 -> n
    const int t  = ty * 16 + tx;
    const int bz = blockIdx.z;
    const int n0 = blockIdx.y * 32;
    const int m0 = blockIdx.x * 32;

    const float* xp = g_xp  + (bz * NN + n0) * DD;
    const float* yp = g_ypb + (bz * NN + m0) * DD;

    // ws2 once (all 256 d)
    {
        float wv = 0.5f * W2[t];
        u64 wp; PK(wp, wv, wv);
        *(u64*)&ws2[2 * t] = wp;
    }

    u64 C0P, C1P;
    PK(C0P, GC0, GC0);
    PK(C1P, GC1, GC1);

    u64 acc0 = 0ull, acc1 = 0ull;   // (a00,a01), (a10,a11)

    const int r  = t >> 3;    // 0..31
    const int cq = t & 7;     // 0..7
    const float* xsp = xs + 2 * ty;
    const float* ysp = ys + 2 * tx;

    #pragma unroll
    for (int c = 0; c < 2; ++c) {
        __syncthreads();   // (c=1: protect prior chunk's reads before refill)
        // Conflict-free transpose fill of this 128-d chunk
        #pragma unroll
        for (int it = 0; it < 4; ++it) {
            int dl = 32 * it + 4 * cq;           // 0..124 within chunk
            int dg = c * DCH + dl;               // global d
            float4 v = *(const float4*)&xp[r * 256 + dg];
            xs[(dl + 0) * SX + r] = v.x;
            xs[(dl + 1) * SX + r] = v.y;
            xs[(dl + 2) * SX + r] = v.z;
            xs[(dl + 3) * SX + r] = v.w;
            float4 u = *(const float4*)&yp[r * 256 + dg];
            ys[(dl + 0) * SX + r] = u.x;
            ys[(dl + 1) * SX + r] = u.y;
            ys[(dl + 2) * SX + r] = u.z;
            ys[(dl + 3) * SX + r] = u.w;
        }
        __syncthreads();

        const float* wc = ws2 + c * 2 * DCH;

        #pragma unroll 8
        for (int d = 0; d < DCH; ++d) {
            float2 xv = *(const float2*)&xsp[d * SX];
            u64 Y = *(const u64*)&ysp[d * SX];
            u64 W = *(const u64*)&wc[2 * d];
            u64 X0, X1;
            PK(X0, xv.x, xv.x);
            PK(X1, xv.y, xv.y);

            #define GEL2(ACC, XB)                               \
            {                                                   \
                u64 H, Q, S, U, T, G;                           \
                float u0, u1, t0, t1;                           \
                F2ADD(H, XB, Y);                                \
                F2MUL(Q, H, H);                                 \
                F2FMA(S, Q, C1P, C0P);                          \
                F2MUL(U, H, S);                                 \
                UNPK(u0, u1, U);                                \
                t0 = tanh_fast(u0);                             \
                t1 = tanh_fast(u1);                             \
                PK(T, t0, t1);                                  \
                F2FMA(G, H, T, H);                              \
                F2FMA(ACC, G, W, ACC);                          \
            }

            GEL2(acc0, X0)
            GEL2(acc1, X1)
            #undef GEL2
        }
    }

    const float bb = b2[0];
    u64 bpair; PK(bpair, bb, bb);
    F2ADD(acc0, acc0, bpair);
    F2ADD(acc1, acc1, bpair);

    const int n = n0 + 2 * ty;
    const int m = m0 + 2 * tx;
    float* orow = out + (size_t)(bz * NN + n) * NN + m;
    *(u64*)&orow[0]  = acc0;
    *(u64*)&orow[NN] = acc1;
}

// ---------------------------------------------------------------------------
extern "C" void kernel_launch(void* const* d_in, const int* in_sizes, int n_in,
                              void* d_out, int out_size)
{
    const float* x  = (const float*)d_in[0];
    const float* y  = (const float*)d_in[1];
    const float* W1 = (const float*)d_in[2];
    const float* b1 = (const float*)d_in[3];
    const float* W2 = (const float*)d_in[4];
    const float* b2 = (const float*)d_in[5];
    float* out = (float*)d_out;

    (void)in_sizes; (void)n_in; (void)out_size;

    const int smem_cross = (2 * DCH * SX + 512) * (int)sizeof(float);
    cudaFuncSetAttribute(cross_kernel,
                         cudaFuncAttributeMaxDynamicSharedMemorySize,
                         smem_cross);

    dim3 gblk(16, 16);
    dim3 ggrid(4, 32, 2);   // both GEMMs in one launch
    gemm_kernel<<<ggrid, gblk>>>(x, y, W1, b1);

    dim3 cblk(16, 16);
    dim3 cgrid(16, 16, 4);  // (m-tiles, n-tiles, batch)
    cross_kernel<<<cgrid, cblk, smem_cross>>>(W2, b2, out);
}